// round 2
// baseline (speedup 1.0000x reference)
#include <cuda_runtime.h>

typedef unsigned long long u64;

#define BATCH   4
#define CHAN    16
#define MAXT    2048
#define FDIM    32
#define TOKENS  256
#define KW      2049
#define HALFK   1024
#define NBF     (BATCH * FDIM)

#define TOK_PER_CHUNK 32
#define NCHUNK        8

// wavelet scratch: normalized (wr, wi) per (b, f_row, k)
__device__ float2 g_wav[NBF * KW];

// ---------------------------------------------------------------------------
// Kernel 1: precompute normalized wavelets
// ---------------------------------------------------------------------------
__global__ void wavelet_kernel(const float* __restrict__ fs,
                               const float* __restrict__ freqs,
                               const float* __restrict__ ncyc)
{
    __shared__ float red[256];
    int bf = blockIdx.x;
    int b = bf >> 5, f = bf & 31;
    int tid = threadIdx.x;

    float fv  = fmaxf(freqs[f], 0.1f);
    float ncv = fmaxf(ncyc[f], 1.0f);
    float fsv = fs[b];
    float w0 = 6.2831855f * fv;          // fp32(2*pi) * f, ref op order
    float sigma = ncv / w0;
    float denom = 2.0f * sigma * sigma;

    float wr[9], wi[9];
    float s = 0.0f;
    #pragma unroll
    for (int it = 0; it < 9; ++it) {
        int k = tid + it * 256;
        wr[it] = 0.0f; wi[it] = 0.0f;
        if (k < KW) {
            float ts = (float)(k - HALFK) / fsv;
            float env = expf(-(ts * ts) / denom);
            float sn, cs;
            sincosf(w0 * ts, &sn, &cs);
            wr[it] = cs * env;
            wi[it] = sn * env;
            s += sqrtf(wr[it] * wr[it] + wi[it] * wi[it]);
        }
    }
    red[tid] = s;
    __syncthreads();
    for (int o = 128; o > 0; o >>= 1) {
        if (tid < o) red[tid] += red[tid + o];
        __syncthreads();
    }
    float norm = red[0] + 1e-8f;

    #pragma unroll
    for (int it = 0; it < 9; ++it) {
        int k = tid + it * 256;
        if (k < KW)
            g_wav[bf * KW + k] = make_float2(wr[it] / norm, wi[it] / norm);
    }
}

// ---------------------------------------------------------------------------
// packed f32x2 helpers
// ---------------------------------------------------------------------------
__device__ __forceinline__ u64 dup2(float x) {
    unsigned int u = __float_as_uint(x);
    u64 r;
    asm("mov.b64 %0, {%1, %1};" : "=l"(r) : "r"(u));
    return r;
}
__device__ __forceinline__ u64 fma2(u64 a, u64 b, u64 c) {
    u64 d;
    asm("fma.rn.f32x2 %0, %1, %2, %3;" : "=l"(d) : "l"(a), "l"(b), "l"(c));
    return d;
}
__device__ __forceinline__ u64 add2(u64 a, u64 b) {
    u64 d;
    asm("add.rn.f32x2 %0, %1, %2;" : "=l"(d) : "l"(a), "l"(b));
    return d;
}
__device__ __forceinline__ float2 unpack2(u64 v) {
    unsigned int lo, hi;
    asm("mov.b64 {%0, %1}, %2;" : "=r"(lo), "=r"(hi) : "l"(v));
    return make_float2(__uint_as_float(lo), __uint_as_float(hi));
}

// TwoSum compensated accumulate: (S, C) += p.  Subtraction via exact
// fma(x, -1, y) so everything stays on the fma pipe (b*-1 is exact).
__device__ __forceinline__ void twosum(u64& S, u64& C, u64 p, u64 neg1) {
    u64 t  = add2(S, p);
    u64 z  = fma2(S, neg1, t);     // t - S
    u64 tz = fma2(z, neg1, t);     // t - z
    u64 e1 = fma2(tz, neg1, S);    // S - (t - z)
    u64 e2 = fma2(z, neg1, p);     // p - z
    C = add2(C, add2(e1, e2));
    S = t;
}

// ---------------------------------------------------------------------------
// bit-exact replication of the reference's fp32 grid arithmetic
// ---------------------------------------------------------------------------
__device__ __forceinline__ float token_gx_exact(int j, float t) {
    float delta = __fdiv_rn(1.0f, 255.0f);            // linspace step
    float step  = __fmul_rn((float)j, delta);         // iota * delta
    float xc    = __fadd_rn(-1.0f, __fmul_rn(step, t));
    return __fmul_rn(__fmul_rn(__fadd_rn(xc, 1.0f), 0.5f), 2047.0f);
}

// smem layout
#define WSLOT      2058                     // nn+2 max (nn <= 2056)
#define WSBYTES    (WSLOT * 8)              // 16464
#define XSMAX      2312
#define SMEM_BYTES (2 * WSBYTES + CHAN * XSMAX * 4)   // 180896

// ---------------------------------------------------------------------------
// Kernel 2
// ---------------------------------------------------------------------------
__global__ void __launch_bounds__(256, 1)
cwt_kernel(const float* __restrict__ x, const float* __restrict__ fs,
           const int* __restrict__ seq_lens, const float* __restrict__ freqs,
           const float* __restrict__ ncyc, float* __restrict__ out)
{
    extern __shared__ char smem[];
    float2* ws0 = (float2*)smem;
    float2* ws1 = (float2*)(smem + WSBYTES);
    float*  xs  = (float*)(smem + 2 * WSBYTES);

    int bf = blockIdx.x;
    int b = bf >> 5, f = bf & 31;
    int chunk = blockIdx.y;
    int tid = threadIdx.x;

    int L = seq_lens[b];
    float Lf = (float)L;

    // ---- ref-exact end_x / t ----
    float aa   = __fadd_rn(Lf, -1.0f);
    float bb   = __fmul_rn(2.0f, aa);
    float cc   = __fdiv_rn(bb, 2047.0f);
    float endx = __fadd_rn(-1.0f, cc);
    float tT   = __fadd_rn(endx, 1.0f);

    // ---- ref-exact gy, vertical blend rows/weights ----
    float yd  = __fdiv_rn(2.0f, 31.0f);
    float ys  = __fmul_rn((float)f, yd);
    float yv  = __fadd_rn(-1.0f, ys);
    float gy  = __fmul_rn(__fmul_rn(__fadd_rn(yv, 1.0f), 0.5f), 31.0f);
    float y0f = floorf(gy);
    int   iy0 = (int)y0f;
    float wy1 = __fadd_rn(gy, -y0f);
    float wy0 = __fadd_rn(1.0f, -wy1);
    int   r0  = iy0;
    int   r1  = iy0 + 1;
    if (r1 > 31) { wy1 = 0.0f; r1 = 31; }

    // ---- half-window from the lower row (larger sigma of the pair) ----
    float fsv = fs[b];
    float fv0  = fmaxf(freqs[r0], 0.1f);
    float ncv0 = fmaxf(ncyc[r0], 1.0f);
    float sig_samp = ncv0 * fsv / (6.2831855f * fv0);
    int hw = min(HALFK, (int)ceilf(6.0f * sig_samp));
    if (hw < 1) hw = 1;
    int n  = 2 * hw + 2;
    int nn = (n + 7) & ~7;

    int j0 = chunk * TOK_PER_CHUNK;
    int t0min = (int)floorf(token_gx_exact(j0, tT));
    int t0max = (int)floorf(token_gx_exact(j0 + TOK_PER_CHUNK - 1, tT));
    int base = t0min - hw;
    int len  = (t0max - t0min) + 2 * hw + 10;         // +8 unroll pad
    int stride = len | 1;

    // stage both wavelet rows over the common index range
    {
        const float2* wavA = g_wav + (b * FDIM + r0) * KW;
        const float2* wavB = g_wav + (b * FDIM + r1) * KW;
        for (int u = tid; u < nn + 2; u += 256) {
            int k = HALFK - hw + u - 2;
            bool ok = (u >= 2) && (k <= KW - 1);
            ws0[u] = ok ? wavA[k] : make_float2(0.0f, 0.0f);
            ws1[u] = ok ? wavB[k] : make_float2(0.0f, 0.0f);
        }
    }
    // stage x slice, zero-padded outside [0, MAXT)
    {
        int c = tid >> 4, l = tid & 15;
        const float* xb = x + (size_t)(b * CHAN + c) * MAXT;
        float* xr = xs + c * stride;
        for (int i = l; i < len; i += 16) {
            int g = base + i;
            xr[i] = (g >= 0 && g < MAXT) ? xb[g] : 0.0f;
        }
    }
    __syncthreads();

    // two tokens per thread
    int c  = tid & 15;
    int tl = tid >> 4;
    int jA = j0 + tl, jB = j0 + tl + 16;

    float gxA = token_gx_exact(jA, tT);
    float gxB = token_gx_exact(jB, tT);
    float x0A = floorf(gxA), x0B = floorf(gxB);
    int t0A = (int)x0A, t0B = (int)x0B;
    float wx1A = __fadd_rn(gxA, -x0A);
    float wx1B = __fadd_rn(gxB, -x0B);
    float wx0A = __fadd_rn(1.0f, -wx1A);
    float wx0B = __fadd_rn(1.0f, -wx1B);
    if (t0A + 1 > MAXT - 1) wx1A = 0.0f;   // ref's valid mask on x1 gather
    if (t0B + 1 > MAXT - 1) wx1B = 0.0f;

    const float* xA = xs + c * stride + (t0A - t0min);
    const float* xB = xs + c * stride + (t0B - t0min);
    const u64* w0u = (const u64*)ws0;
    const u64* w1u = (const u64*)ws1;

    u64 neg1 = dup2(-1.0f);
    // master + compensation accumulators: token{A,B} x row{0,1} x col{0,1}
    u64 SA00=0, SA01=0, SA10=0, SA11=0, SB00=0, SB01=0, SB10=0, SB11=0;
    u64 CA00=0, CA01=0, CA10=0, CA11=0, CB00=0, CB01=0, CB10=0, CB11=0;
    u64 wp0 = 0ull, wp1 = 0ull;            // ws[1] == 0 pad

    for (int ub = 0; ub < nn; ub += 8) {
        u64 aA00=0, aA01=0, aA10=0, aA11=0;
        u64 aB00=0, aB01=0, aB10=0, aB11=0;
        #pragma unroll
        for (int k = 0; k < 8; ++k) {
            int u = ub + k;
            u64 w0 = w0u[u + 2];
            u64 w1 = w1u[u + 2];
            u64 xa = dup2(xA[u]);
            u64 xb = dup2(xB[u]);
            aA00 = fma2(w0,  xa, aA00);
            aA01 = fma2(wp0, xa, aA01);
            aA10 = fma2(w1,  xa, aA10);
            aA11 = fma2(wp1, xa, aA11);
            aB00 = fma2(w0,  xb, aB00);
            aB01 = fma2(wp0, xb, aB01);
            aB10 = fma2(w1,  xb, aB10);
            aB11 = fma2(wp1, xb, aB11);
            wp0 = w0; wp1 = w1;
        }
        twosum(SA00, CA00, aA00, neg1);
        twosum(SA01, CA01, aA01, neg1);
        twosum(SA10, CA10, aA10, neg1);
        twosum(SA11, CA11, aA11, neg1);
        twosum(SB00, CB00, aB00, neg1);
        twosum(SB01, CB01, aB01, neg1);
        twosum(SB10, CB10, aB10, neg1);
        twosum(SB11, CB11, aB11, neg1);
    }

    float2 zA00 = unpack2(add2(SA00, CA00));
    float2 zA01 = unpack2(add2(SA01, CA01));
    float2 zA10 = unpack2(add2(SA10, CA10));
    float2 zA11 = unpack2(add2(SA11, CA11));
    float2 zB00 = unpack2(add2(SB00, CB00));
    float2 zB01 = unpack2(add2(SB01, CB01));
    float2 zB10 = unpack2(add2(SB10, CB10));
    float2 zB11 = unpack2(add2(SB11, CB11));

    // ref-exact bilinear combine: ((t1 + t2) + t3) + t4
    float w00A = __fmul_rn(wy0, wx0A), w01A = __fmul_rn(wy0, wx1A);
    float w10A = __fmul_rn(wy1, wx0A), w11A = __fmul_rn(wy1, wx1A);
    float w00B = __fmul_rn(wy0, wx0B), w01B = __fmul_rn(wy0, wx1B);
    float w10B = __fmul_rn(wy1, wx0B), w11B = __fmul_rn(wy1, wx1B);

    float rA = __fadd_rn(__fadd_rn(__fadd_rn(__fmul_rn(zA00.x, w00A),
               __fmul_rn(zA01.x, w01A)), __fmul_rn(zA10.x, w10A)),
               __fmul_rn(zA11.x, w11A));
    float iA = __fadd_rn(__fadd_rn(__fadd_rn(__fmul_rn(zA00.y, w00A),
               __fmul_rn(zA01.y, w01A)), __fmul_rn(zA10.y, w10A)),
               __fmul_rn(zA11.y, w11A));
    float rB = __fadd_rn(__fadd_rn(__fadd_rn(__fmul_rn(zB00.x, w00B),
               __fmul_rn(zB01.x, w01B)), __fmul_rn(zB10.x, w10B)),
               __fmul_rn(zB11.x, w11B));
    float iB = __fadd_rn(__fadd_rn(__fadd_rn(__fmul_rn(zB00.y, w00B),
               __fmul_rn(zB01.y, w01B)), __fmul_rn(zB10.y, w10B)),
               __fmul_rn(zB11.y, w11B));

    float magA = __fsqrt_rn(__fadd_rn(__fadd_rn(__fmul_rn(rA, rA),
                                                __fmul_rn(iA, iA)), 1e-8f));
    float magB = __fsqrt_rn(__fadd_rn(__fadd_rn(__fmul_rn(rB, rB),
                                                __fmul_rn(iB, iB)), 1e-8f));
    float phA = __fdiv_rn(atan2f(iA, rA), 3.14159274f);
    float phB = __fdiv_rn(atan2f(iB, rB), 3.14159274f);

    size_t obase = ((size_t)(b * CHAN + c) * 2) * FDIM + f;
    out[(obase) * TOKENS + jA]        = magA;
    out[(obase + FDIM) * TOKENS + jA] = phA;
    out[(obase) * TOKENS + jB]        = magB;
    out[(obase + FDIM) * TOKENS + jB] = phB;
}

// ---------------------------------------------------------------------------
extern "C" void kernel_launch(void* const* d_in, const int* in_sizes, int n_in,
                              void* d_out, int out_size)
{
    const float* x    = (const float*)d_in[0];
    const float* fs   = (const float*)d_in[1];
    const int*   sl   = (const int*)d_in[2];
    const float* fr   = (const float*)d_in[3];
    const float* nc   = (const float*)d_in[4];
    float* out = (float*)d_out;

    cudaFuncSetAttribute(cwt_kernel, cudaFuncAttributeMaxDynamicSharedMemorySize,
                         SMEM_BYTES);

    wavelet_kernel<<<NBF, 256>>>(fs, fr, nc);
    dim3 grid(NBF, NCHUNK);
    cwt_kernel<<<grid, 256, SMEM_BYTES>>>(x, fs, sl, fr, nc, out);
}

// round 3
// speedup vs baseline: 1.1822x; 1.1822x over previous
#include <cuda_runtime.h>

typedef unsigned long long u64;

#define BATCH   4
#define CHAN    16
#define MAXT    2048
#define FDIM    32
#define TOKENS  256
#define KW      2049
#define HALFK   1024
#define NBF     (BATCH * FDIM)

#define TOK_PER_CHUNK 32
#define NCHUNK        8

// wavelet scratch: normalized (wr, wi) per (b, f_row, k)
__device__ float2 g_wav[NBF * KW];

// ---------------------------------------------------------------------------
// Kernel 1: precompute normalized wavelets
// ---------------------------------------------------------------------------
__global__ void wavelet_kernel(const float* __restrict__ fs,
                               const float* __restrict__ freqs,
                               const float* __restrict__ ncyc)
{
    __shared__ float red[256];
    int bf = blockIdx.x;
    int b = bf >> 5, f = bf & 31;
    int tid = threadIdx.x;

    float fv  = fmaxf(freqs[f], 0.1f);
    float ncv = fmaxf(ncyc[f], 1.0f);
    float fsv = fs[b];
    float w0 = 6.2831855f * fv;          // fp32(2*pi) * f, ref op order
    float sigma = ncv / w0;
    float denom = 2.0f * sigma * sigma;

    float wr[9], wi[9];
    float s = 0.0f;
    #pragma unroll
    for (int it = 0; it < 9; ++it) {
        int k = tid + it * 256;
        wr[it] = 0.0f; wi[it] = 0.0f;
        if (k < KW) {
            float ts = (float)(k - HALFK) / fsv;
            float env = expf(-(ts * ts) / denom);
            float sn, cs;
            sincosf(w0 * ts, &sn, &cs);
            wr[it] = cs * env;
            wi[it] = sn * env;
            s += sqrtf(wr[it] * wr[it] + wi[it] * wi[it]);
        }
    }
    red[tid] = s;
    __syncthreads();
    for (int o = 128; o > 0; o >>= 1) {
        if (tid < o) red[tid] += red[tid + o];
        __syncthreads();
    }
    float norm = red[0] + 1e-8f;

    #pragma unroll
    for (int it = 0; it < 9; ++it) {
        int k = tid + it * 256;
        if (k < KW)
            g_wav[bf * KW + k] = make_float2(wr[it] / norm, wi[it] / norm);
    }
}

// ---------------------------------------------------------------------------
// packed f32x2 helpers
// ---------------------------------------------------------------------------
__device__ __forceinline__ u64 dup2(float x) {
    unsigned int u = __float_as_uint(x);
    u64 r;
    asm("mov.b64 %0, {%1, %1};" : "=l"(r) : "r"(u));
    return r;
}
__device__ __forceinline__ u64 fma2(u64 a, u64 b, u64 c) {
    u64 d;
    asm("fma.rn.f32x2 %0, %1, %2, %3;" : "=l"(d) : "l"(a), "l"(b), "l"(c));
    return d;
}
__device__ __forceinline__ u64 add2(u64 a, u64 b) {
    u64 d;
    asm("add.rn.f32x2 %0, %1, %2;" : "=l"(d) : "l"(a), "l"(b));
    return d;
}
__device__ __forceinline__ float2 unpack2(u64 v) {
    unsigned int lo, hi;
    asm("mov.b64 {%0, %1}, %2;" : "=r"(lo), "=r"(hi) : "l"(v));
    return make_float2(__uint_as_float(lo), __uint_as_float(hi));
}

// TwoSum compensated accumulate: (S, C) += p.  Subtractions via exact
// fma(x, -1, y) so everything stays on the fma pipe.
__device__ __forceinline__ void twosum(u64& S, u64& C, u64 p, u64 neg1) {
    u64 t  = add2(S, p);
    u64 z  = fma2(S, neg1, t);     // t - S
    u64 tz = fma2(z, neg1, t);     // t - z
    u64 e1 = fma2(tz, neg1, S);    // S - (t - z)
    u64 e2 = fma2(z, neg1, p);     // p - z
    C = add2(C, add2(e1, e2));
    S = t;
}

// ---------------------------------------------------------------------------
// bit-exact replication of the reference's fp32 grid arithmetic
// ---------------------------------------------------------------------------
__device__ __forceinline__ float token_gx_exact(int j, float t) {
    float delta = __fdiv_rn(1.0f, 255.0f);            // linspace step
    float step  = __fmul_rn((float)j, delta);         // iota * delta
    float xc    = __fadd_rn(-1.0f, __fmul_rn(step, t));
    return __fmul_rn(__fmul_rn(__fadd_rn(xc, 1.0f), 0.5f), 2047.0f);
}

// smem layout (nn is padded to a multiple of 64 so each tap-half is mult of 32)
#define WSLOT      2118                     // >= nn+2 max (nn <= 2112)
#define WSBYTES    (WSLOT * 8)              // 16944
#define XSMAX      2368                     // span(<=250) + nn(<=2112) + pad, odd
#define SMEM_BYTES (2 * WSBYTES + CHAN * XSMAX * 4)   // 185440

// ---------------------------------------------------------------------------
// Kernel 2: 512 threads = 16 chan x 16 token-lanes x 2 tap-halves.
// Each thread: 2 tokens x (2 rows x 2 cols) packed-complex accumulators over
// its half of the tap range; halves reduced through smem at the end.
// ---------------------------------------------------------------------------
__global__ void __launch_bounds__(512, 1)
cwt_kernel(const float* __restrict__ x, const float* __restrict__ fs,
           const int* __restrict__ seq_lens, const float* __restrict__ freqs,
           const float* __restrict__ ncyc, float* __restrict__ out)
{
    extern __shared__ char smem[];
    float2* ws0 = (float2*)smem;
    float2* ws1 = (float2*)(smem + WSBYTES);
    float*  xs  = (float*)(smem + 2 * WSBYTES);

    int bf = blockIdx.x;
    int b = bf >> 5, f = bf & 31;
    int chunk = blockIdx.y;
    int tid = threadIdx.x;

    int L = seq_lens[b];
    float Lf = (float)L;

    // ---- ref-exact end_x / t ----
    float aa   = __fadd_rn(Lf, -1.0f);
    float bb   = __fmul_rn(2.0f, aa);
    float cc   = __fdiv_rn(bb, 2047.0f);
    float endx = __fadd_rn(-1.0f, cc);
    float tT   = __fadd_rn(endx, 1.0f);

    // ---- ref-exact gy, vertical blend rows/weights ----
    float yd  = __fdiv_rn(2.0f, 31.0f);
    float ys  = __fmul_rn((float)f, yd);
    float yv  = __fadd_rn(-1.0f, ys);
    float gy  = __fmul_rn(__fmul_rn(__fadd_rn(yv, 1.0f), 0.5f), 31.0f);
    float y0f = floorf(gy);
    int   iy0 = (int)y0f;
    float wy1 = __fadd_rn(gy, -y0f);
    float wy0 = __fadd_rn(1.0f, -wy1);
    int   r0  = iy0;
    int   r1  = iy0 + 1;
    if (r1 > 31) { wy1 = 0.0f; r1 = 31; }

    // ---- half-window from the lower row (larger sigma of the pair) ----
    float fsv = fs[b];
    float fv0  = fmaxf(freqs[r0], 0.1f);
    float ncv0 = fmaxf(ncyc[r0], 1.0f);
    float sig_samp = ncv0 * fsv / (6.2831855f * fv0);
    int hw = min(HALFK, (int)ceilf(6.0f * sig_samp));
    if (hw < 1) hw = 1;
    int n  = 2 * hw + 2;
    int nn = (n + 63) & ~63;               // multiple of 64
    int n2 = nn >> 1;                      // per-half taps, multiple of 32

    int j0 = chunk * TOK_PER_CHUNK;
    int t0min = (int)floorf(token_gx_exact(j0, tT));
    int t0max = (int)floorf(token_gx_exact(j0 + TOK_PER_CHUNK - 1, tT));
    int base = t0min - hw;
    int len  = (t0max - t0min) + nn + 4;
    int stride = len | 1;

    // stage both wavelet rows, zero-padded: ws[u] = w[1024-hw+u-2] for u in [2, n]
    {
        const float2* wavA = g_wav + (b * FDIM + r0) * KW;
        const float2* wavB = g_wav + (b * FDIM + r1) * KW;
        for (int u = tid; u < nn + 2; u += 512) {
            int k = HALFK - hw + u - 2;
            bool ok = (u >= 2) && (u <= n) && (k <= KW - 1);
            ws0[u] = ok ? wavA[k] : make_float2(0.0f, 0.0f);
            ws1[u] = ok ? wavB[k] : make_float2(0.0f, 0.0f);
        }
    }
    // stage x slice, zero-padded outside [0, MAXT)
    {
        int c = tid & 15, l = tid >> 4;     // 32 loaders per channel row
        const float* xb = x + (size_t)(b * CHAN + c) * MAXT;
        float* xr = xs + c * stride;
        for (int i = l; i < len; i += 32) {
            int g = base + i;
            xr[i] = (g >= 0 && g < MAXT) ? xb[g] : 0.0f;
        }
    }
    __syncthreads();

    // thread mapping: c, token-lane, tap-half
    int c    = tid & 15;
    int tl   = (tid >> 4) & 15;
    int half = tid >> 8;
    int jA = j0 + tl, jB = j0 + tl + 16;

    float gxA = token_gx_exact(jA, tT);
    float gxB = token_gx_exact(jB, tT);
    float x0A = floorf(gxA), x0B = floorf(gxB);
    int t0A = (int)x0A, t0B = (int)x0B;
    float wx1A = __fadd_rn(gxA, -x0A);
    float wx1B = __fadd_rn(gxB, -x0B);
    float wx0A = __fadd_rn(1.0f, -wx1A);
    float wx0B = __fadd_rn(1.0f, -wx1B);
    if (t0A + 1 > MAXT - 1) wx1A = 0.0f;   // ref's valid mask on x1 gather
    if (t0B + 1 > MAXT - 1) wx1B = 0.0f;

    int u0 = half * n2;
    const float* xA = xs + c * stride + (t0A - t0min) + u0;
    const float* xB = xs + c * stride + (t0B - t0min) + u0;
    const u64* w0u = (const u64*)ws0 + u0;
    const u64* w1u = (const u64*)ws1 + u0;

    u64 neg1 = dup2(-1.0f);
    u64 SA00=0, SA01=0, SA10=0, SA11=0, SB00=0, SB01=0, SB10=0, SB11=0;
    u64 CA00=0, CA01=0, CA10=0, CA11=0, CB00=0, CB01=0, CB10=0, CB11=0;
    // col t0 uses ws[u+2]; col t0+1 uses ws[u+1] (carried register)
    u64 wp0 = w0u[1], wp1 = w1u[1];

    for (int ub = 0; ub < n2; ub += 32) {
        u64 aA00=0, aA01=0, aA10=0, aA11=0;
        u64 aB00=0, aB01=0, aB10=0, aB11=0;
        #pragma unroll 8
        for (int k = 0; k < 32; ++k) {
            int u = ub + k;
            u64 w0 = w0u[u + 2];
            u64 w1 = w1u[u + 2];
            u64 xa = dup2(xA[u]);
            u64 xb = dup2(xB[u]);
            aA00 = fma2(w0,  xa, aA00);
            aA01 = fma2(wp0, xa, aA01);
            aA10 = fma2(w1,  xa, aA10);
            aA11 = fma2(wp1, xa, aA11);
            aB00 = fma2(w0,  xb, aB00);
            aB01 = fma2(wp0, xb, aB01);
            aB10 = fma2(w1,  xb, aB10);
            aB11 = fma2(wp1, xb, aB11);
            wp0 = w0; wp1 = w1;
        }
        twosum(SA00, CA00, aA00, neg1);
        twosum(SA01, CA01, aA01, neg1);
        twosum(SA10, CA10, aA10, neg1);
        twosum(SA11, CA11, aA11, neg1);
        twosum(SB00, CB00, aB00, neg1);
        twosum(SB01, CB01, aB01, neg1);
        twosum(SB10, CB10, aB10, neg1);
        twosum(SB11, CB11, aB11, neg1);
    }

    // fold S+C per accumulator
    u64 P[8];
    P[0] = add2(SA00, CA00); P[1] = add2(SA01, CA01);
    P[2] = add2(SA10, CA10); P[3] = add2(SA11, CA11);
    P[4] = add2(SB00, CB00); P[5] = add2(SB01, CB01);
    P[6] = add2(SB10, CB10); P[7] = add2(SB11, CB11);

    // cross-half reduction through smem (xs region is free now)
    __syncthreads();
    u64* red = (u64*)xs;
    int pidx = tid & 255;
    if (half == 1) {
        #pragma unroll
        for (int a = 0; a < 8; ++a) red[pidx * 8 + a] = P[a];
    }
    __syncthreads();
    if (half == 1) return;

    #pragma unroll
    for (int a = 0; a < 8; ++a) P[a] = add2(P[a], red[pidx * 8 + a]);

    float2 zA00 = unpack2(P[0]), zA01 = unpack2(P[1]);
    float2 zA10 = unpack2(P[2]), zA11 = unpack2(P[3]);
    float2 zB00 = unpack2(P[4]), zB01 = unpack2(P[5]);
    float2 zB10 = unpack2(P[6]), zB11 = unpack2(P[7]);

    // ref-exact bilinear combine: ((t1 + t2) + t3) + t4
    float w00A = __fmul_rn(wy0, wx0A), w01A = __fmul_rn(wy0, wx1A);
    float w10A = __fmul_rn(wy1, wx0A), w11A = __fmul_rn(wy1, wx1A);
    float w00B = __fmul_rn(wy0, wx0B), w01B = __fmul_rn(wy0, wx1B);
    float w10B = __fmul_rn(wy1, wx0B), w11B = __fmul_rn(wy1, wx1B);

    float rA = __fadd_rn(__fadd_rn(__fadd_rn(__fmul_rn(zA00.x, w00A),
               __fmul_rn(zA01.x, w01A)), __fmul_rn(zA10.x, w10A)),
               __fmul_rn(zA11.x, w11A));
    float iA = __fadd_rn(__fadd_rn(__fadd_rn(__fmul_rn(zA00.y, w00A),
               __fmul_rn(zA01.y, w01A)), __fmul_rn(zA10.y, w10A)),
               __fmul_rn(zA11.y, w11A));
    float rB = __fadd_rn(__fadd_rn(__fadd_rn(__fmul_rn(zB00.x, w00B),
               __fmul_rn(zB01.x, w01B)), __fmul_rn(zB10.x, w10B)),
               __fmul_rn(zB11.x, w11B));
    float iB = __fadd_rn(__fadd_rn(__fadd_rn(__fmul_rn(zB00.y, w00B),
               __fmul_rn(zB01.y, w01B)), __fmul_rn(zB10.y, w10B)),
               __fmul_rn(zB11.y, w11B));

    float magA = __fsqrt_rn(__fadd_rn(__fadd_rn(__fmul_rn(rA, rA),
                                                __fmul_rn(iA, iA)), 1e-8f));
    float magB = __fsqrt_rn(__fadd_rn(__fadd_rn(__fmul_rn(rB, rB),
                                                __fmul_rn(iB, iB)), 1e-8f));
    float phA = __fdiv_rn(atan2f(iA, rA), 3.14159274f);
    float phB = __fdiv_rn(atan2f(iB, rB), 3.14159274f);

    size_t obase = ((size_t)(b * CHAN + c) * 2) * FDIM + f;
    out[(obase) * TOKENS + jA]        = magA;
    out[(obase + FDIM) * TOKENS + jA] = phA;
    out[(obase) * TOKENS + jB]        = magB;
    out[(obase + FDIM) * TOKENS + jB] = phB;
}

// ---------------------------------------------------------------------------
extern "C" void kernel_launch(void* const* d_in, const int* in_sizes, int n_in,
                              void* d_out, int out_size)
{
    const float* x    = (const float*)d_in[0];
    const float* fs   = (const float*)d_in[1];
    const int*   sl   = (const int*)d_in[2];
    const float* fr   = (const float*)d_in[3];
    const float* nc   = (const float*)d_in[4];
    float* out = (float*)d_out;

    cudaFuncSetAttribute(cwt_kernel, cudaFuncAttributeMaxDynamicSharedMemorySize,
                         SMEM_BYTES);

    wavelet_kernel<<<NBF, 256>>>(fs, fr, nc);
    dim3 grid(NBF, NCHUNK);
    cwt_kernel<<<grid, 512, SMEM_BYTES>>>(x, fs, sl, fr, nc, out);
}